// round 10
// baseline (speedup 1.0000x reference)
#include <cuda_runtime.h>
#include <cuda_fp16.h>
#include <cstdint>

#define T_TOK 8192
#define HID   1024
#define NEXP  8
#define INTERN 2816
#define BM 128
#define BK 32                  // k halves per stage
#define NSTG 5
#define MAXTILES 136
#define SLOT_CAP (MAXTILES*BM)
#define PITCH  40              // A smem pitch (halves)
#define PITCHB1 72             // gemm1 B smem pitch (halves): 64 data + 8 pad
#define PITCHB2 136            // gemm2 B smem pitch (halves): 128 data + 8 pad

// ---------------- device scratch -------------------------------------------
__device__ int    g_top_idx[T_TOK*2];
__device__ float  g_top_w[T_TOK*2];
__device__ int    g_cnt[NEXP];
__device__ int    g_fill[NEXP];
__device__ int    g_slot_token[SLOT_CAP];
__device__ float  g_slot_w[SLOT_CAP];
__device__ __half g_xh[(size_t)T_TOK*HID];
__device__ __half g_wgh[(size_t)NEXP*HID*INTERN];   // native [e][k=H][n=I], fp16
__device__ __half g_wuh[(size_t)NEXP*HID*INTERN];
__device__ __half g_wdh[(size_t)NEXP*INTERN*HID];   // native [e][k=I][n=H], fp16
__device__ __half g_interh[(size_t)SLOT_CAP*INTERN];

// ---------------- helpers ----------------------------------------------------
__device__ __forceinline__ void cp16(uint32_t dst, const void* src, int sz){
    asm volatile("cp.async.cg.shared.global [%0], [%1], 16, %2;\n" :: "r"(dst), "l"(src), "r"(sz));
}
#define CP_COMMIT asm volatile("cp.async.commit_group;\n" ::: "memory")
#define CP_WAIT1  asm volatile("cp.async.wait_group 1;\n" ::: "memory")

#define MMA_F16(c,a,b) \
  asm volatile("mma.sync.aligned.m16n8k16.row.col.f32.f16.f16.f32 " \
               "{%0,%1,%2,%3},{%4,%5,%6,%7},{%8,%9},{%0,%1,%2,%3};" \
               : "+f"((c)[0]),"+f"((c)[1]),"+f"((c)[2]),"+f"((c)[3]) \
               : "r"((a)[0]),"r"((a)[1]),"r"((a)[2]),"r"((a)[3]), \
                 "r"((b)[0]),"r"((b)[1]))

#define LDSM4(r, addr) \
  asm volatile("ldmatrix.sync.aligned.m8n8.x4.shared.b16 {%0,%1,%2,%3}, [%4];" \
               : "=r"((r)[0]),"=r"((r)[1]),"=r"((r)[2]),"=r"((r)[3]) : "r"(addr))

#define LDSM4T(r, addr) \
  asm volatile("ldmatrix.sync.aligned.m8n8.x4.trans.shared.b16 {%0,%1,%2,%3}, [%4];" \
               : "=r"((r)[0]),"=r"((r)[1]),"=r"((r)[2]),"=r"((r)[3]) : "r"(addr))

__device__ __forceinline__ uint32_t s2u(const void* p){
    uint32_t a;
    asm("{ .reg .u64 t; cvta.to.shared.u64 t, %1; cvt.u32.u64 %0, t; }" : "=r"(a) : "l"(p));
    return a;
}

struct TileInfo { int e, slot0, ebase, ecnt; };
__device__ __forceinline__ TileInfo resolve_tile(int bx){
    TileInfo ti; ti.e = -1; ti.slot0 = 0; ti.ebase = 0; ti.ecnt = 0;
    int tacc = 0, base = 0;
    #pragma unroll
    for (int i=0;i<NEXP;i++){
        int c = g_cnt[i];
        int nt = (c + BM - 1) >> 7;
        if (ti.e < 0 && bx < tacc + nt){
            ti.e = i; ti.slot0 = base + (bx - tacc)*BM; ti.ebase = base; ti.ecnt = c;
        }
        tacc += nt; base += nt*BM;
    }
    return ti;
}

// ---------------- kernel 0: streaming convert (NO transpose) -------------------
// z<8: wg, z<16: wu, z<24: wd (layout-preserving fp32->fp16), z==24: xh + out zero + init
__global__ void k_pre(const float* __restrict__ x,  const float* __restrict__ wg,
                      const float* __restrict__ wu, const float* __restrict__ wd,
                      float* __restrict__ out){
    int z = blockIdx.z;
    int tid = threadIdx.x;
    if (z < 24){
        const size_t HI = (size_t)HID*INTERN;
        const float* src; __half* dst;
        if (z < 8){       src = wg + (size_t)z*HI;      dst = g_wgh + (size_t)z*HI; }
        else if (z < 16){ src = wu + (size_t)(z-8)*HI;  dst = g_wuh + (size_t)(z-8)*HI; }
        else {            src = wd + (size_t)(z-16)*HI; dst = g_wdh + (size_t)(z-16)*HI; }
        size_t i = ((size_t)blockIdx.y*gridDim.x + blockIdx.x)*256 + tid;  // over HI/4
        float4 v = ((const float4*)src)[i];
        __half2 h0 = __floats2half2_rn(v.x, v.y);
        __half2 h1 = __floats2half2_rn(v.z, v.w);
        ((__half2*)dst)[2*i]   = h0;
        ((__half2*)dst)[2*i+1] = h1;
    } else {
        if (blockIdx.x==0 && blockIdx.y==0 && tid<NEXP){ g_cnt[tid]=0; g_fill[tid]=0; }
        int bid = blockIdx.y*gridDim.x + blockIdx.x;
        const int NH2 = T_TOK*HID/2;
        const int STRD = 88*32*256;
        for (int i = bid*256 + tid; i < NH2; i += STRD){
            float2 v = ((const float2*)x)[i];
            ((__half2*)g_xh)[i] = __floats2half2_rn(v.x, v.y);
            ((float2*)out)[i] = make_float2(0.f, 0.f);
        }
    }
}

// ---------------- kernel 1: router (exact fp32) -------------------------------
__global__ void k_router(const float* __restrict__ x, const float* __restrict__ rw){
    int warp = (blockIdx.x*blockDim.x + threadIdx.x) >> 5;
    int lane = threadIdx.x & 31;
    if (warp >= T_TOK) return;
    const float* xr = x + (size_t)warp*HID;
    float acc[NEXP];
    #pragma unroll
    for (int e=0;e<NEXP;e++) acc[e]=0.f;
    for (int j=lane; j<HID; j+=32){
        float v = xr[j];
        const float* r = rw + j*NEXP;
        #pragma unroll
        for (int e=0;e<NEXP;e++) acc[e] += v*r[e];
    }
    #pragma unroll
    for (int o=16;o>0;o>>=1)
        #pragma unroll
        for (int e=0;e<NEXP;e++) acc[e] += __shfl_down_sync(0xffffffffu, acc[e], o);
    if (lane==0){
        int i0=0; float l0=acc[0];
        #pragma unroll
        for (int e=1;e<NEXP;e++) if (acc[e]>l0){ l0=acc[e]; i0=e; }
        int i1=-1; float l1=-1e30f;
        #pragma unroll
        for (int e=0;e<NEXP;e++) if (e!=i0 && acc[e]>l1){ l1=acc[e]; i1=e; }
        float w0 = 1.f/(1.f + expf(l1 - l0));
        g_top_idx[warp*2+0]=i0; g_top_idx[warp*2+1]=i1;
        g_top_w[warp*2+0]=w0;   g_top_w[warp*2+1]=1.f-w0;
        atomicAdd(&g_cnt[i0],1); atomicAdd(&g_cnt[i1],1);
    }
}

// ---------------- kernel 2: scatter -------------------------------------------
__global__ void k_scatter(){
    int t = blockIdx.x*blockDim.x + threadIdx.x;
    if (t>=T_TOK) return;
    int base[NEXP]; int b=0;
    #pragma unroll
    for (int e=0;e<NEXP;e++){ base[e]=b; b += ((g_cnt[e]+BM-1)>>7)<<7; }
    #pragma unroll
    for (int k=0;k<2;k++){
        int e = g_top_idx[t*2+k];
        int pos = atomicAdd(&g_fill[e],1);
        int slot = base[e]+pos;
        g_slot_token[slot]=t;
        g_slot_w[slot]=g_top_w[t*2+k];
    }
}

// ============ GEMM1: warp 32x(32g+32u), B via ldmatrix.trans, 5-stage/2kt =====
#define G1_ASTG (BM*PITCH)                 // 5120 halves
#define G1_BSTG (64*PITCHB1)               // 4608 halves: rows 0-31 gate, 32-63 up
#define G1_SMEM ((G1_ASTG+G1_BSTG)*NSTG*2) // 97280 bytes

__global__ void __launch_bounds__(256,2) k_gemm1(){
    extern __shared__ __half smh[];
    TileInfo ti = resolve_tile(blockIdx.x);
    if (ti.e < 0) return;
    int slot0 = ti.slot0;
    int n0 = blockIdx.y*64;
    int tid=threadIdx.x, lane=tid&31, warp=tid>>5;
    int wm = warp>>1, wn = warp&1;
    uint32_t sA = s2u(smh);
    uint32_t sB = sA + NSTG*G1_ASTG*2;

    // ldmatrix lane components
    int lAr = lane & 15,               lAk = 8*(lane>>4);           // A (non-trans)
    int lBr = (lane&7) + 8*((lane>>3)&1), lBn = 8*(lane>>4);        // B (trans): k-row, n-col

    // A staging: thread t -> row t&127, chunk pair (t>>7)*2 (+0,+1) [conflict-free]
    int arow = tid & 127, ah = (tid>>7)*16;   // halves offset of first chunk
    int vrow = (slot0 + arow - ti.ebase) < ti.ecnt;
    int tok = vrow ? g_slot_token[slot0+arow] : 0;
    const __half* asrc = g_xh + (size_t)tok*HID + ah;
    int asz = vrow ? 16 : 0;
    // B staging: thread t -> k-row t>>3 (0-31), chunk t&7 [conflict-free]
    int br = tid>>3, bc = (tid&7)*8;   // bc in halves
    const __half* gsrc = g_wgh + (size_t)ti.e*HID*INTERN + (size_t)br*INTERN + n0 + bc;
    const __half* usrc = g_wuh + (size_t)ti.e*HID*INTERN + (size_t)br*INTERN + n0 + bc;

    float cg[2][4][4], cu[2][4][4];
    #pragma unroll
    for (int i=0;i<2;i++)
        #pragma unroll
        for (int j=0;j<4;j++)
            #pragma unroll
            for (int r=0;r<4;r++){ cg[i][j][r]=0.f; cu[i][j][r]=0.f; }

    auto stage = [&](int s, int k0){
        uint32_t ad = sA + (uint32_t)(s*G1_ASTG + arow*PITCH + ah)*2;
        cp16(ad,      asrc + k0,     asz);
        cp16(ad + 16, asrc + k0 + 8, asz);
        size_t koff = (size_t)k0*INTERN;
        uint32_t bd = sB + (uint32_t)(s*G1_BSTG + br*PITCHB1 + bc)*2;
        cp16(bd,                 gsrc + koff, 16);
        cp16(bd + 32*PITCHB1*2,  usrc + koff, 16);
        CP_COMMIT;
    };

    stage(0, 0); stage(1, BK); stage(2, 2*BK);
    const int NT = HID/BK;   // 32, even
    for (int j=0; j<NT; j+=2){
        CP_WAIT1;
        __syncthreads();
        int k3 = j+3, k4 = j+4;
        if (k3 < NT) stage(k3%NSTG, k3*BK); else CP_COMMIT;
        if (k4 < NT) stage(k4%NSTG, k4*BK); else CP_COMMIT;
        #pragma unroll
        for (int h=0; h<2; h++){
            int s = (j+h)%NSTG;
            uint32_t aoff = sA + (uint32_t)(s*G1_ASTG)*2;
            uint32_t boff = sB + (uint32_t)(s*G1_BSTG)*2;
            #pragma unroll
            for (int ks=0; ks<2; ks++){
                int kb = ks*16;
                uint32_t a0[4], a1[4];
                LDSM4(a0, aoff + (uint32_t)((wm*32     + lAr)*PITCH + kb + lAk)*2);
                LDSM4(a1, aoff + (uint32_t)((wm*32 +16 + lAr)*PITCH + kb + lAk)*2);
                #pragma unroll
                for (int nq=0;nq<2;nq++){
                    int nb = wn*32 + nq*16 + lBn;
                    uint32_t bg[4], bu[4];
                    LDSM4T(bg, boff + (uint32_t)((     kb + lBr)*PITCHB1 + nb)*2);
                    LDSM4T(bu, boff + (uint32_t)((32 + kb + lBr)*PITCHB1 + nb)*2);
                    MMA_F16(cg[0][nq*2+0], a0, bg+0);
                    MMA_F16(cg[0][nq*2+1], a0, bg+2);
                    MMA_F16(cg[1][nq*2+0], a1, bg+0);
                    MMA_F16(cg[1][nq*2+1], a1, bg+2);
                    MMA_F16(cu[0][nq*2+0], a0, bu+0);
                    MMA_F16(cu[0][nq*2+1], a0, bu+2);
                    MMA_F16(cu[1][nq*2+0], a1, bu+0);
                    MMA_F16(cu[1][nq*2+1], a1, bu+2);
                }
            }
        }
    }
    int g8 = lane>>2, tg = lane&3;
    #pragma unroll
    for (int mi=0;mi<2;mi++)
        #pragma unroll
        for (int ni=0;ni<4;ni++)
            #pragma unroll
            for (int rr=0;rr<2;rr++){
                int row = wm*32 + mi*16 + g8 + rr*8;
                int col = wn*32 + ni*8 + 2*tg;
                float g0 = cg[mi][ni][rr*2+0], u0 = cu[mi][ni][rr*2+0];
                float g1 = cg[mi][ni][rr*2+1], u1 = cu[mi][ni][rr*2+1];
                float v0 = u0 * (g0 / (1.f + expf(-g0)));
                float v1 = u1 * (g1 / (1.f + expf(-g1)));
                *(__half2*)(g_interh + (size_t)(slot0+row)*INTERN + n0 + col)
                    = __floats2half2_rn(v0, v1);
            }
}

// ============ GEMM2: warp 32x64, B via ldmatrix.trans, fused combine ==========
#define G2_ASTG (BM*PITCH)                 // 5120 halves
#define G2_BSTG (32*PITCHB2)               // 4352 halves
#define G2_SMEM ((G2_ASTG+G2_BSTG)*NSTG*2) // 94720 bytes

__global__ void __launch_bounds__(256,2) k_gemm2(float* __restrict__ out){
    extern __shared__ __half smh[];
    TileInfo ti = resolve_tile(blockIdx.x);
    if (ti.e < 0) return;
    int slot0 = ti.slot0;
    int n0 = blockIdx.y*128;
    int tid=threadIdx.x, lane=tid&31, warp=tid>>5;
    int wm = warp>>1, wn = warp&1;
    uint32_t sA = s2u(smh);
    uint32_t sB = sA + NSTG*G2_ASTG*2;

    int lAr = lane & 15,               lAk = 8*(lane>>4);
    int lBr = (lane&7) + 8*((lane>>3)&1), lBn = 8*(lane>>4);

    int arow = tid & 127, ah = (tid>>7)*16;
    const __half* asrc = g_interh + (size_t)(slot0+arow)*INTERN + ah;
    int br = tid>>3, bc = (tid&7)*8;
    const __half* bsrc = g_wdh + (size_t)ti.e*INTERN*HID + (size_t)br*HID + n0 + bc;

    float cc[2][8][4];
    #pragma unroll
    for (int i=0;i<2;i++)
        #pragma unroll
        for (int j=0;j<8;j++)
            #pragma unroll
            for (int r=0;r<4;r++) cc[i][j][r]=0.f;

    auto stage = [&](int s, int k0){
        uint32_t ad = sA + (uint32_t)(s*G2_ASTG + arow*PITCH + ah)*2;
        cp16(ad,      asrc + k0,     16);
        cp16(ad + 16, asrc + k0 + 8, 16);
        size_t koff = (size_t)k0*HID;
        uint32_t bd = sB + (uint32_t)(s*G2_BSTG + br*PITCHB2 + bc)*2;
        cp16(bd,       bsrc + koff,      16);
        cp16(bd + 128, bsrc + koff + 64, 16);   // chunk +8 (64 halves = 128B)
        CP_COMMIT;
    };

    stage(0, 0); stage(1, BK); stage(2, 2*BK);
    const int NT = INTERN/BK;   // 88, even
    for (int j=0; j<NT; j+=2){
        CP_WAIT1;
        __syncthreads();
        int k3 = j+3, k4 = j+4;
        if (k3 < NT) stage(k3%NSTG, k3*BK); else CP_COMMIT;
        if (k4 < NT) stage(k4%NSTG, k4*BK); else CP_COMMIT;
        #pragma unroll
        for (int h=0; h<2; h++){
            int s = (j+h)%NSTG;
            uint32_t aoff = sA + (uint32_t)(s*G2_ASTG)*2;
            uint32_t boff = sB + (uint32_t)(s*G2_BSTG)*2;
            #pragma unroll
            for (int ks=0; ks<2; ks++){
                int kb = ks*16;
                uint32_t a0[4], a1[4];
                LDSM4(a0, aoff + (uint32_t)((wm*32     + lAr)*PITCH + kb + lAk)*2);
                LDSM4(a1, aoff + (uint32_t)((wm*32 +16 + lAr)*PITCH + kb + lAk)*2);
                #pragma unroll
                for (int nq=0;nq<4;nq++){
                    int nb = wn*64 + nq*16 + lBn;
                    uint32_t bf[4];
                    LDSM4T(bf, boff + (uint32_t)((kb + lBr)*PITCHB2 + nb)*2);
                    MMA_F16(cc[0][nq*2+0], a0, bf+0);
                    MMA_F16(cc[0][nq*2+1], a0, bf+2);
                    MMA_F16(cc[1][nq*2+0], a1, bf+0);
                    MMA_F16(cc[1][nq*2+1], a1, bf+2);
                }
            }
        }
    }
    // fused combine: out[token] += w_slot * val (2 commutative fp32 adds/elt)
    int g8 = lane>>2, tg = lane&3;
    #pragma unroll
    for (int mi=0;mi<2;mi++){
        #pragma unroll
        for (int rr=0;rr<2;rr++){
            int row = wm*32 + mi*16 + g8 + rr*8;
            if ((slot0 + row - ti.ebase) >= ti.ecnt) continue;
            int tokn = g_slot_token[slot0+row];
            float w  = g_slot_w[slot0+row];
            float* orow = out + (size_t)tokn*HID + n0;
            #pragma unroll
            for (int nj=0;nj<8;nj++){
                int col = wn*64 + (nj>>1)*16 + (nj&1)*8 + 2*tg;
                atomicAdd(orow + col,     w*cc[mi][nj][rr*2+0]);
                atomicAdd(orow + col + 1, w*cc[mi][nj][rr*2+1]);
            }
        }
    }
}

// ---------------- launch -----------------------------------------------------
extern "C" void kernel_launch(void* const* d_in, const int* in_sizes, int n_in,
                              void* d_out, int out_size){
    const float* x  = (const float*)d_in[0];
    const float* rw = (const float*)d_in[1];
    const float* wg = (const float*)d_in[2];
    const float* wu = (const float*)d_in[3];
    const float* wd = (const float*)d_in[4];
    float* out = (float*)d_out;

    cudaFuncSetAttribute(k_gemm1, cudaFuncAttributeMaxDynamicSharedMemorySize, G1_SMEM);
    cudaFuncSetAttribute(k_gemm2, cudaFuncAttributeMaxDynamicSharedMemorySize, G2_SMEM);

    k_pre<<<dim3(88, 32, 25), 256>>>(x, wg, wu, wd, out);
    k_router<<<T_TOK/8, 256>>>(x, rw);
    k_scatter<<<(T_TOK+255)/256, 256>>>();
    k_gemm1<<<dim3(MAXTILES, INTERN/64), 256, G1_SMEM>>>();
    k_gemm2<<<dim3(MAXTILES, HID/128), 256, G2_SMEM>>>(out);
}

// round 11
// speedup vs baseline: 1.0470x; 1.0470x over previous
#include <cuda_runtime.h>
#include <cuda_fp16.h>
#include <cstdint>

#define T_TOK 8192
#define HID   1024
#define NEXP  8
#define INTERN 2816
#define BM 128
#define BK 32                  // k halves per stage
#define NSTG 5
#define MAXTILES 136
#define SLOT_CAP (MAXTILES*BM)
#define PITCH 40               // smem row pitch in halves (80B)

// ---------------- device scratch -------------------------------------------
__device__ int    g_top_idx[T_TOK*2];
__device__ float  g_top_w[T_TOK*2];
__device__ int    g_cnt[NEXP];
__device__ int    g_fill[NEXP];
__device__ int    g_slot_token[SLOT_CAP];
__device__ float  g_slot_w[SLOT_CAP];
__device__ __half g_xh[(size_t)T_TOK*HID];
__device__ __half g_wgT[(size_t)NEXP*INTERN*HID];   // [e][n=I][k=H]
__device__ __half g_wuT[(size_t)NEXP*INTERN*HID];
__device__ __half g_wdT[(size_t)NEXP*HID*INTERN];   // [e][n=H][k=I]
__device__ __half g_interh[(size_t)SLOT_CAP*INTERN];

// ---------------- helpers ----------------------------------------------------
__device__ __forceinline__ void cp16(uint32_t dst, const void* src, int sz){
    asm volatile("cp.async.cg.shared.global [%0], [%1], 16, %2;\n" :: "r"(dst), "l"(src), "r"(sz));
}
#define CP_COMMIT asm volatile("cp.async.commit_group;\n" ::: "memory")
#define CP_WAIT1  asm volatile("cp.async.wait_group 1;\n" ::: "memory")

#define MMA_F16(c,a,b) \
  asm volatile("mma.sync.aligned.m16n8k16.row.col.f32.f16.f16.f32 " \
               "{%0,%1,%2,%3},{%4,%5,%6,%7},{%8,%9},{%0,%1,%2,%3};" \
               : "+f"((c)[0]),"+f"((c)[1]),"+f"((c)[2]),"+f"((c)[3]) \
               : "r"((a)[0]),"r"((a)[1]),"r"((a)[2]),"r"((a)[3]), \
                 "r"((b)[0]),"r"((b)[1]))

#define LDSM4(r, addr) \
  asm volatile("ldmatrix.sync.aligned.m8n8.x4.shared.b16 {%0,%1,%2,%3}, [%4];" \
               : "=r"((r)[0]),"=r"((r)[1]),"=r"((r)[2]),"=r"((r)[3]) : "r"(addr))

__device__ __forceinline__ uint32_t s2u(const void* p){
    uint32_t a;
    asm("{ .reg .u64 t; cvta.to.shared.u64 t, %1; cvt.u32.u64 %0, t; }" : "=r"(a) : "l"(p));
    return a;
}

struct TileInfo { int e, slot0, ebase, ecnt; };
__device__ __forceinline__ TileInfo resolve_tile(int bx){
    TileInfo ti; ti.e = -1; ti.slot0 = 0; ti.ebase = 0; ti.ecnt = 0;
    int tacc = 0, base = 0;
    #pragma unroll
    for (int i=0;i<NEXP;i++){
        int c = g_cnt[i];
        int nt = (c + BM - 1) >> 7;
        if (ti.e < 0 && bx < tacc + nt){
            ti.e = i; ti.slot0 = base + (bx - tacc)*BM; ti.ebase = base; ti.ecnt = c;
        }
        tacc += nt; base += nt*BM;
    }
    return ti;
}

// ---------------- kernel 0: fused pre-pass (fast transpose) --------------------
// Transpose tile: 64 (K) x 32 (N). Reads: 32 float4-coalesced rows.
// Writes: 8 halves (16B) per thread, 128B contiguous per dst row.
// z<8: wg, z<16: wu, z<24: wd, z==24: x->fp16 + out zero + counter init.
__global__ void k_pre(const float* __restrict__ x,  const float* __restrict__ wg,
                      const float* __restrict__ wu, const float* __restrict__ wd,
                      float* __restrict__ out){
    int z = blockIdx.z;
    int tx = threadIdx.x, ty = threadIdx.y;     // 32 x 8
    int tid = ty*32 + tx;
    if (z < 24){
        __shared__ float t[64][33];
        const float* src; __half* dst; int K, N, xt, yt;
        int tl = blockIdx.y*88 + blockIdx.x;    // 0..1407
        if (z < 8){       src = wg + (size_t)z*HID*INTERN;      dst = g_wgT + (size_t)z*INTERN*HID;
                          K = HID; N = INTERN; xt = blockIdx.x; yt = blockIdx.y; }           // 88 x 16
        else if (z < 16){ int e = z-8;  src = wu + (size_t)e*HID*INTERN; dst = g_wuT + (size_t)e*INTERN*HID;
                          K = HID; N = INTERN; xt = blockIdx.x; yt = blockIdx.y; }
        else {            int e = z-16; src = wd + (size_t)e*INTERN*HID; dst = g_wdT + (size_t)e*HID*INTERN;
                          K = INTERN; N = HID;  xt = tl & 31;   yt = tl >> 5; }              // 32 x 44
        int x0 = xt*32, y0 = yt*64;             // x0: n-offset, y0: k-offset
        // read 64 k-rows x 32 n-cols
        #pragma unroll
        for (int j=0;j<8;j++)
            t[ty+8*j][tx] = src[(size_t)(y0+ty+8*j)*N + x0+tx];
        __syncthreads();
        // write: dst row n = tid>>3 (0..31), k-chunk (tid&7)*8 -> 8 halves (16B)
        int n = tid>>3, kc = (tid&7)*8;
        __half2 h[4];
        #pragma unroll
        for (int i=0;i<4;i++)
            h[i] = __floats2half2_rn(t[kc+2*i][n], t[kc+2*i+1][n]);
        *(uint4*)(dst + (size_t)(x0+n)*K + y0 + kc) = *(uint4*)h;
    } else {
        if (blockIdx.x==0 && blockIdx.y==0 && tid<NEXP){ g_cnt[tid]=0; g_fill[tid]=0; }
        int bid = blockIdx.y*gridDim.x + blockIdx.x;
        const int NH2 = T_TOK*HID/2;
        const int STRD = 88*16*256;
        for (int i = bid*256 + tid; i < NH2; i += STRD){
            float2 v = ((const float2*)x)[i];
            ((__half2*)g_xh)[i] = __floats2half2_rn(v.x, v.y);
            ((float2*)out)[i] = make_float2(0.f, 0.f);
        }
    }
}

// ---------------- kernel 1: router (exact fp32) -------------------------------
__global__ void k_router(const float* __restrict__ x, const float* __restrict__ rw){
    int warp = (blockIdx.x*blockDim.x + threadIdx.x) >> 5;
    int lane = threadIdx.x & 31;
    if (warp >= T_TOK) return;
    const float* xr = x + (size_t)warp*HID;
    float acc[NEXP];
    #pragma unroll
    for (int e=0;e<NEXP;e++) acc[e]=0.f;
    for (int j=lane; j<HID; j+=32){
        float v = xr[j];
        const float* r = rw + j*NEXP;
        #pragma unroll
        for (int e=0;e<NEXP;e++) acc[e] += v*r[e];
    }
    #pragma unroll
    for (int o=16;o>0;o>>=1)
        #pragma unroll
        for (int e=0;e<NEXP;e++) acc[e] += __shfl_down_sync(0xffffffffu, acc[e], o);
    if (lane==0){
        int i0=0; float l0=acc[0];
        #pragma unroll
        for (int e=1;e<NEXP;e++) if (acc[e]>l0){ l0=acc[e]; i0=e; }
        int i1=-1; float l1=-1e30f;
        #pragma unroll
        for (int e=0;e<NEXP;e++) if (e!=i0 && acc[e]>l1){ l1=acc[e]; i1=e; }
        float w0 = 1.f/(1.f + expf(l1 - l0));
        g_top_idx[warp*2+0]=i0; g_top_idx[warp*2+1]=i1;
        g_top_w[warp*2+0]=w0;   g_top_w[warp*2+1]=1.f-w0;
        atomicAdd(&g_cnt[i0],1); atomicAdd(&g_cnt[i1],1);
    }
}

// ---------------- kernel 2: scatter -------------------------------------------
__global__ void k_scatter(){
    int t = blockIdx.x*blockDim.x + threadIdx.x;
    if (t>=T_TOK) return;
    int base[NEXP]; int b=0;
    #pragma unroll
    for (int e=0;e<NEXP;e++){ base[e]=b; b += ((g_cnt[e]+BM-1)>>7)<<7; }
    #pragma unroll
    for (int k=0;k<2;k++){
        int e = g_top_idx[t*2+k];
        int pos = atomicAdd(&g_fill[e],1);
        int slot = base[e]+pos;
        g_slot_token[slot]=t;
        g_slot_w[slot]=g_top_w[t*2+k];
    }
}

// ============ GEMM1: 256 thr, warp 32x(32g+32u), 5-stage, sync per 2 kt =======
#define G1_ASTG (BM*PITCH)                 // 5120 halves
#define G1_BSTG (128*PITCH)                // 5120 halves
#define G1_SMEM ((G1_ASTG+G1_BSTG)*NSTG*2) // 102400 bytes

__global__ void __launch_bounds__(256,2) k_gemm1(){
    extern __shared__ __half smh[];
    TileInfo ti = resolve_tile(blockIdx.x);
    if (ti.e < 0) return;
    int slot0 = ti.slot0;
    int n0 = blockIdx.y*64;
    int tid=threadIdx.x, lane=tid&31, warp=tid>>5;
    int wm = warp>>1, wn = warp&1;
    uint32_t sA = s2u(smh);
    uint32_t sB = sA + NSTG*G1_ASTG*2;

    int lAr = lane & 15,              lAk = 8*(lane>>4);
    int lBr = (lane&7) + 8*(lane>>4), lBk = 8*((lane>>3)&1);

    int arow = tid>>1, ak = (tid&1)*16;
    int vrow = (slot0 + arow - ti.ebase) < ti.ecnt;
    int tok = vrow ? g_slot_token[slot0+arow] : 0;
    const __half* asrc = g_xh + (size_t)tok*HID + ak;
    int asz = vrow ? 16 : 0;
    int brow = tid>>1, bk = (tid&1)*16;
    const __half* bsrc = ((brow<64)? g_wgT + (size_t)ti.e*INTERN*HID + (size_t)(n0+brow)*HID
                                   : g_wuT + (size_t)ti.e*INTERN*HID + (size_t)(n0+brow-64)*HID) + bk;

    float cg[2][4][4], cu[2][4][4];
    #pragma unroll
    for (int i=0;i<2;i++)
        #pragma unroll
        for (int j=0;j<4;j++)
            #pragma unroll
            for (int r=0;r<4;r++){ cg[i][j][r]=0.f; cu[i][j][r]=0.f; }

    auto stage = [&](int s, int k0){
        uint32_t ad = sA + (uint32_t)(s*G1_ASTG + arow*PITCH + ak)*2;
        cp16(ad,      asrc + k0,     asz);
        cp16(ad + 16, asrc + k0 + 8, asz);
        uint32_t bd = sB + (uint32_t)(s*G1_BSTG + brow*PITCH + bk)*2;
        cp16(bd,      bsrc + k0,     16);
        cp16(bd + 16, bsrc + k0 + 8, 16);
        CP_COMMIT;
    };

    stage(0, 0); stage(1, BK); stage(2, 2*BK);
    const int NT = HID/BK;   // 32, even
    for (int j=0; j<NT; j+=2){
        CP_WAIT1;                              // stages j, j+1 resident
        __syncthreads();
        int k3 = j+3, k4 = j+4;
        if (k3 < NT) stage(k3%NSTG, k3*BK); else CP_COMMIT;
        if (k4 < NT) stage(k4%NSTG, k4*BK); else CP_COMMIT;
        #pragma unroll
        for (int h=0; h<2; h++){
            int s = (j+h)%NSTG;
            uint32_t aoff = sA + (uint32_t)(s*G1_ASTG)*2;
            uint32_t boff = sB + (uint32_t)(s*G1_BSTG)*2;
            #pragma unroll
            for (int ks=0; ks<2; ks++){
                int kb = ks*16;
                uint32_t a0[4], a1[4];
                LDSM4(a0, aoff + (uint32_t)((wm*32     + lAr)*PITCH + kb + lAk)*2);
                LDSM4(a1, aoff + (uint32_t)((wm*32 +16 + lAr)*PITCH + kb + lAk)*2);
                #pragma unroll
                for (int nq=0;nq<2;nq++){
                    int c0 = wn*32 + nq*16;
                    uint32_t bg[4], bu[4];
                    LDSM4(bg, boff + (uint32_t)((c0    + lBr)*PITCH + kb + lBk)*2);
                    LDSM4(bu, boff + (uint32_t)((c0+64 + lBr)*PITCH + kb + lBk)*2);
                    MMA_F16(cg[0][nq*2+0], a0, bg+0);
                    MMA_F16(cg[0][nq*2+1], a0, bg+2);
                    MMA_F16(cg[1][nq*2+0], a1, bg+0);
                    MMA_F16(cg[1][nq*2+1], a1, bg+2);
                    MMA_F16(cu[0][nq*2+0], a0, bu+0);
                    MMA_F16(cu[0][nq*2+1], a0, bu+2);
                    MMA_F16(cu[1][nq*2+0], a1, bu+0);
                    MMA_F16(cu[1][nq*2+1], a1, bu+2);
                }
            }
        }
    }
    int g8 = lane>>2, tg = lane&3;
    #pragma unroll
    for (int mi=0;mi<2;mi++)
        #pragma unroll
        for (int ni=0;ni<4;ni++)
            #pragma unroll
            for (int rr=0;rr<2;rr++){
                int row = wm*32 + mi*16 + g8 + rr*8;
                int col = wn*32 + ni*8 + 2*tg;
                float g0 = cg[mi][ni][rr*2+0], u0 = cu[mi][ni][rr*2+0];
                float g1 = cg[mi][ni][rr*2+1], u1 = cu[mi][ni][rr*2+1];
                float v0 = u0 * (g0 / (1.f + expf(-g0)));
                float v1 = u1 * (g1 / (1.f + expf(-g1)));
                *(__half2*)(g_interh + (size_t)(slot0+row)*INTERN + n0 + col)
                    = __floats2half2_rn(v0, v1);
            }
}

// ============ GEMM2: 256 thr, warp 32x64, 5-stage/2kt, fused combine ==========
#define G2_ASTG (BM*PITCH)                 // 5120 halves
#define G2_BSTG (128*PITCH)                // 5120 halves
#define G2_SMEM ((G2_ASTG+G2_BSTG)*NSTG*2) // 102400 bytes

__global__ void __launch_bounds__(256,2) k_gemm2(float* __restrict__ out){
    extern __shared__ __half smh[];
    TileInfo ti = resolve_tile(blockIdx.x);
    if (ti.e < 0) return;
    int slot0 = ti.slot0;
    int n0 = blockIdx.y*128;
    int tid=threadIdx.x, lane=tid&31, warp=tid>>5;
    int wm = warp>>1, wn = warp&1;
    uint32_t sA = s2u(smh);
    uint32_t sB = sA + NSTG*G2_ASTG*2;

    int lAr = lane & 15,              lAk = 8*(lane>>4);
    int lBr = (lane&7) + 8*(lane>>4), lBk = 8*((lane>>3)&1);

    int arow = tid>>1, ak = (tid&1)*16;
    const __half* asrc = g_interh + (size_t)(slot0+arow)*INTERN + ak;
    int brow = tid>>1, bk = (tid&1)*16;
    const __half* bsrc = g_wdT + (size_t)ti.e*HID*INTERN + (size_t)(n0+brow)*INTERN + bk;

    float cc[2][8][4];
    #pragma unroll
    for (int i=0;i<2;i++)
        #pragma unroll
        for (int j=0;j<8;j++)
            #pragma unroll
            for (int r=0;r<4;r++) cc[i][j][r]=0.f;

    auto stage = [&](int s, int k0){
        uint32_t ad = sA + (uint32_t)(s*G2_ASTG + arow*PITCH + ak)*2;
        cp16(ad,      asrc + k0,     16);
        cp16(ad + 16, asrc + k0 + 8, 16);
        uint32_t bd = sB + (uint32_t)(s*G2_BSTG + brow*PITCH + bk)*2;
        cp16(bd,      bsrc + k0,     16);
        cp16(bd + 16, bsrc + k0 + 8, 16);
        CP_COMMIT;
    };

    stage(0, 0); stage(1, BK); stage(2, 2*BK);
    const int NT = INTERN/BK;   // 88, even
    for (int j=0; j<NT; j+=2){
        CP_WAIT1;
        __syncthreads();
        int k3 = j+3, k4 = j+4;
        if (k3 < NT) stage(k3%NSTG, k3*BK); else CP_COMMIT;
        if (k4 < NT) stage(k4%NSTG, k4*BK); else CP_COMMIT;
        #pragma unroll
        for (int h=0; h<2; h++){
            int s = (j+h)%NSTG;
            uint32_t aoff = sA + (uint32_t)(s*G2_ASTG)*2;
            uint32_t boff = sB + (uint32_t)(s*G2_BSTG)*2;
            #pragma unroll
            for (int ks=0; ks<2; ks++){
                int kb = ks*16;
                uint32_t a0[4], a1[4];
                LDSM4(a0, aoff + (uint32_t)((wm*32     + lAr)*PITCH + kb + lAk)*2);
                LDSM4(a1, aoff + (uint32_t)((wm*32 +16 + lAr)*PITCH + kb + lAk)*2);
                #pragma unroll
                for (int nq=0;nq<4;nq++){
                    int c0 = wn*64 + nq*16;
                    uint32_t bf[4];
                    LDSM4(bf, boff + (uint32_t)((c0 + lBr)*PITCH + kb + lBk)*2);
                    MMA_F16(cc[0][nq*2+0], a0, bf+0);
                    MMA_F16(cc[0][nq*2+1], a0, bf+2);
                    MMA_F16(cc[1][nq*2+0], a1, bf+0);
                    MMA_F16(cc[1][nq*2+1], a1, bf+2);
                }
            }
        }
    }
    // fused combine: out[token] += w_slot * val (2 commutative fp32 adds/elt)
    int g8 = lane>>2, tg = lane&3;
    #pragma unroll
    for (int mi=0;mi<2;mi++){
        #pragma unroll
        for (int rr=0;rr<2;rr++){
            int row = wm*32 + mi*16 + g8 + rr*8;
            if ((slot0 + row - ti.ebase) >= ti.ecnt) continue;
            int tokn = g_slot_token[slot0+row];
            float w  = g_slot_w[slot0+row];
            float* orow = out + (size_t)tokn*HID + n0;
            #pragma unroll
            for (int nj=0;nj<8;nj++){
                int col = wn*64 + (nj>>1)*16 + (nj&1)*8 + 2*tg;
                atomicAdd(orow + col,     w*cc[mi][nj][rr*2+0]);
                atomicAdd(orow + col + 1, w*cc[mi][nj][rr*2+1]);
            }
        }
    }
}

// ---------------- launch -----------------------------------------------------
extern "C" void kernel_launch(void* const* d_in, const int* in_sizes, int n_in,
                              void* d_out, int out_size){
    const float* x  = (const float*)d_in[0];
    const float* rw = (const float*)d_in[1];
    const float* wg = (const float*)d_in[2];
    const float* wu = (const float*)d_in[3];
    const float* wd = (const float*)d_in[4];
    float* out = (float*)d_out;

    cudaFuncSetAttribute(k_gemm1, cudaFuncAttributeMaxDynamicSharedMemorySize, G1_SMEM);
    cudaFuncSetAttribute(k_gemm2, cudaFuncAttributeMaxDynamicSharedMemorySize, G2_SMEM);

    k_pre<<<dim3(88, 16, 25), dim3(32,8)>>>(x, wg, wu, wd, out);
    k_router<<<T_TOK/8, 256>>>(x, rw);
    k_scatter<<<(T_TOK+255)/256, 256>>>();
    k_gemm1<<<dim3(MAXTILES, INTERN/64), 256, G1_SMEM>>>();
    k_gemm2<<<dim3(MAXTILES, HID/128), 256, G2_SMEM>>>(out);
}